// round 15
// baseline (speedup 1.0000x reference)
#include <cuda_runtime.h>
#include <cuda_bf16.h>
#include <cstdint>

// Problem constants
#define Mv 8192
#define Nv 8192
#define Cv 80

#define ZSPLIT 16              // m-windows (512 rows each) in write kernel
#define MWIN   (Mv / ZSPLIT)   // 512
#define ROWS_T 64              // rows per vmat block
#define SPAD 81                // smem row stride -> conflict-free column walks
#define NSEG 8                 // 1024-column output segments
#define NCONS (NSEG * Cv * ZSPLIT)   // 10240 write blocks

// Scratch (no allocation allowed in kernel_launch)
__device__ float g_V[Cv][Nv];     // V[c][n] = base[n] - pc[n][c]

// Gating state (zero at load; reset by last consumer every run)
__device__ volatile int g_seg_done[NSEG];   // 16 producers per segment
__device__ int          g_cons_done;

// Phase 1: 128 blocks compute V (64 rows each). blockDim = 256.
// PDL trigger fires at ENTRY so the write kernel co-schedules immediately;
// g_V ordering is handled by per-segment flags, not the trigger.
__global__ void __launch_bounds__(256) phase1_kernel(const float* __restrict__ pc) {
    cudaTriggerProgrammaticLaunchCompletion();

    __shared__ float sp[ROWS_T * SPAD];       // 20.7 KB tile
    __shared__ float sS[ROWS_T][4];           // partial max-sums
    __shared__ float sP[ROWS_T][4];           // partial products
    __shared__ float sb[ROWS_T];              // base per row

    const int n0 = blockIdx.x * ROWS_T;
    const int t  = threadIdx.x;

    // Load tile (64 rows x 80 floats = 1280 float4), coalesced.
    const float4* src = reinterpret_cast<const float4*>(pc + (size_t)n0 * Cv);
#pragma unroll
    for (int i = 0; i < 5; i++) {
        int q4 = i * 256 + t;
        float4 v = src[q4];
        int row = q4 / 20, c4 = q4 % 20;
        float* d = &sp[row * SPAD + c4 * 4];
        d[0] = v.x; d[1] = v.y; d[2] = v.z; d[3] = v.w;
    }
    __syncthreads();

    // Each thread: 20 classes of one row. S = sum max(x,0); P = prod(1+e^{-|x|}).
    const int r = t & 63;
    const int q = t >> 6;
    float S = 0.0f, P = 1.0f;
#pragma unroll 5
    for (int j = 0; j < 20; j++) {
        float x = sp[r * SPAD + q * 20 + j];
        S += fmaxf(x, 0.0f);
        P *= 1.0f + __expf(-fabsf(x));
    }
    sS[r][q] = S;
    sP[r][q] = P;
    __syncthreads();

    // Rows reduce: base = sum(S) + log(prod(P)) -> one LG2 per row.
    if (t < ROWS_T) {
        float Ssum  = sS[t][0] + sS[t][1] + sS[t][2] + sS[t][3];
        float Pprod = (sP[t][0] * sP[t][1]) * (sP[t][2] * sP[t][3]);
        sb[t] = Ssum + __logf(Pprod);
    }
    __syncthreads();

    // V[c][n0+r] = base[r] - x ; 64-float coalesced runs per c.
#pragma unroll 4
    for (int idx = t; idx < Cv * ROWS_T; idx += 256) {
        int c = idx >> 6, rr = idx & 63;
        g_V[c][n0 + rr] = sb[rr] - sp[rr * SPAD + c];
    }

    // Release this 1024-column segment (16 producers per segment).
    __threadfence();
    __syncthreads();
    if (t == 0) atomicAdd((int*)&g_seg_done[blockIdx.x >> 4], 1);
}

// Write kernel: grid = (Nv/1024, Cv, ZSPLIT), block = 256. PDL secondary.
// Preamble: ballot membership scan of input g (overlaps with phase1).
// Then spin briefly on this segment's flag, load the V[c] slice, and stream
// it to the matched rows with evict-first stores.
__global__ void __launch_bounds__(256) write_kernel(const int* __restrict__ g,
                                                    float* __restrict__ out) {
    __shared__ int rows[MWIN];
    __shared__ int cnt_s;

    cudaGridDependencySynchronize();   // cheap: primary triggers at entry

    const int c  = blockIdx.y;
    const int m0 = blockIdx.z * MWIN;
    const int t  = threadIdx.x;
    const int w  = t >> 5;      // warp 0..7
    const int l  = t & 31;
    const int x  = blockIdx.x;  // column segment

    if (t == 0) cnt_s = 0;
    __syncthreads();

    // Membership scan over input g (independent of phase1's output).
#pragma unroll
    for (int half = 0; half < 2; half++) {
        int m = m0 + w * 64 + half * 32 + l;
        unsigned b = __ballot_sync(0xFFFFFFFFu, g[m] == c);
        int nmatch = __popc(b);
        int base = 0;
        if (l == 0 && nmatch) base = atomicAdd(&cnt_s, nmatch);
        base = __shfl_sync(0xFFFFFFFFu, base, 0);
        if (b & (1u << l)) {
            int pos = __popc(b & ((1u << l) - 1));
            rows[base + pos] = m;
        }
    }

    // Wait for this segment's V producers (brief under overlap).
    if (t == 0) {
        while (g_seg_done[x] < 16) __nanosleep(64);
        __threadfence();
    }
    __syncthreads();

    const int n0 = x * 1024 + t * 4;
    const float4 v = *reinterpret_cast<const float4*>(&g_V[c][n0]);

    const int nrows = cnt_s;
    float4* out4 = reinterpret_cast<float4*>(out);
    const size_t col = (size_t)(n0 >> 2);

    for (int k = 0; k < nrows; k++) {
        int m = rows[k];                                // LDS broadcast
        __stcs(&out4[(size_t)m * (Nv / 4) + col], v);   // streaming STG.128
    }

    // Last consumer resets gating state for the next graph replay.
    __syncthreads();
    if (t == 0) {
        int done = atomicAdd(&g_cons_done, 1);
        if (done == NCONS - 1) {
            for (int s = 0; s < NSEG; s++) g_seg_done[s] = 0;
            g_cons_done = 0;
        }
    }
}

extern "C" void kernel_launch(void* const* d_in, const int* in_sizes, int n_in,
                              void* d_out, int out_size) {
    const int*   g;
    const float* pc;
    if (in_sizes[0] == Mv) {
        g  = (const int*)d_in[0];
        pc = (const float*)d_in[1];
    } else {
        g  = (const int*)d_in[1];
        pc = (const float*)d_in[0];
    }
    float* out = (float*)d_out;

    phase1_kernel<<<128, 256>>>(pc);

    // PDL launch: secondary co-schedules as soon as primaries trigger (entry);
    // g_V ordering enforced by per-segment flags inside the kernel.
    cudaLaunchConfig_t cfg = {};
    cfg.gridDim  = dim3(NSEG, Cv, ZSPLIT);
    cfg.blockDim = dim3(256, 1, 1);
    cfg.stream   = 0;
    cudaLaunchAttribute attr[1];
    attr[0].id = cudaLaunchAttributeProgrammaticStreamSerialization;
    attr[0].val.programmaticStreamSerializationAllowed = 1;
    cfg.attrs    = attr;
    cfg.numAttrs = 1;
    cudaLaunchKernelEx(&cfg, write_kernel, g, out);
}

// round 16
// speedup vs baseline: 1.1301x; 1.1301x over previous
#include <cuda_runtime.h>
#include <cuda_bf16.h>
#include <cstdint>

// Problem constants
#define Mv 8192
#define Nv 8192
#define Cv 80

#define ZSPLIT 16         // m-windows (512 rows each) in write kernel
#define MWIN   (Mv / ZSPLIT)   // 512
#define ROWS_T 64         // rows per vmat block
#define SPAD 81           // smem row stride -> conflict-free column walks

// Scratch (no allocation allowed in kernel_launch)
__device__ float g_V[Cv][Nv];     // V[c][n] = base[n] - pc[n][c]

// Phase 1: 128 blocks compute V (64 rows each). blockDim = 256.
__global__ void __launch_bounds__(256) phase1_kernel(const float* __restrict__ pc) {
    __shared__ float sp[ROWS_T * SPAD];       // 20.7 KB tile
    __shared__ float sS[ROWS_T][4];           // partial max-sums
    __shared__ float sP[ROWS_T][4];           // partial products
    __shared__ float sb[ROWS_T];              // base per row

    const int n0 = blockIdx.x * ROWS_T;
    const int t  = threadIdx.x;

    // Load tile (64 rows x 80 floats = 1280 float4), coalesced.
    const float4* src = reinterpret_cast<const float4*>(pc + (size_t)n0 * Cv);
#pragma unroll
    for (int i = 0; i < 5; i++) {
        int q4 = i * 256 + t;
        float4 v = src[q4];
        int row = q4 / 20, c4 = q4 % 20;
        float* d = &sp[row * SPAD + c4 * 4];
        d[0] = v.x; d[1] = v.y; d[2] = v.z; d[3] = v.w;
    }
    __syncthreads();

    // Each thread: 20 classes of one row. S = sum max(x,0); P = prod(1+e^{-|x|}).
    const int r = t & 63;
    const int q = t >> 6;
    float S = 0.0f, P = 1.0f;
#pragma unroll 5
    for (int j = 0; j < 20; j++) {
        float x = sp[r * SPAD + q * 20 + j];
        S += fmaxf(x, 0.0f);
        P *= 1.0f + __expf(-fabsf(x));
    }
    sS[r][q] = S;
    sP[r][q] = P;
    __syncthreads();

    // Rows reduce: base = sum(S) + log(prod(P)) -> one LG2 per row.
    if (t < ROWS_T) {
        float Ssum  = sS[t][0] + sS[t][1] + sS[t][2] + sS[t][3];
        float Pprod = (sP[t][0] * sP[t][1]) * (sP[t][2] * sP[t][3]);
        sb[t] = Ssum + __logf(Pprod);
    }
    __syncthreads();

    // V[c][n0+r] = base[r] - x ; 64-float coalesced runs per c.
#pragma unroll 4
    for (int idx = t; idx < Cv * ROWS_T; idx += 256) {
        int c = idx >> 6, rr = idx & 63;
        g_V[c][n0 + rr] = sb[rr] - sp[rr * SPAD + c];
    }
    cudaTriggerProgrammaticLaunchCompletion();
}

// Write kernel: grid = (Nv/1024, Cv, ZSPLIT), block = 256. PDL secondary.
// Preamble (before grid-dependency sync): ballot membership scan of the
// INPUT array g — overlaps with phase1's drain. Then sync, load the V[c]
// slice, and stream it to the matched rows with evict-first stores.
__global__ void __launch_bounds__(256) write_kernel(const int* __restrict__ g,
                                                    float* __restrict__ out) {
    __shared__ int rows[MWIN];
    __shared__ int cnt_s;

    const int c  = blockIdx.y;
    const int m0 = blockIdx.z * MWIN;
    const int t  = threadIdx.x;
    const int w  = t >> 5;      // warp 0..7
    const int l  = t & 31;

    if (t == 0) cnt_s = 0;
    __syncthreads();

    // Membership scan over input g (independent of phase1's output).
#pragma unroll
    for (int half = 0; half < 2; half++) {
        int m = m0 + w * 64 + half * 32 + l;
        unsigned b = __ballot_sync(0xFFFFFFFFu, g[m] == c);
        int nmatch = __popc(b);
        int base = 0;
        if (l == 0 && nmatch) base = atomicAdd(&cnt_s, nmatch);
        base = __shfl_sync(0xFFFFFFFFu, base, 0);
        if (b & (1u << l)) {
            int pos = __popc(b & ((1u << l) - 1));
            rows[base + pos] = m;
        }
    }
    __syncthreads();

    // Now wait for phase1's V writes, then read our slice.
    cudaGridDependencySynchronize();

    const int n0 = blockIdx.x * 1024 + t * 4;
    const float4 v = *reinterpret_cast<const float4*>(&g_V[c][n0]);

    const int nrows = cnt_s;
    float4* out4 = reinterpret_cast<float4*>(out);
    const size_t col = (size_t)(n0 >> 2);

    for (int k = 0; k < nrows; k++) {
        int m = rows[k];                                // LDS broadcast
        __stcs(&out4[(size_t)m * (Nv / 4) + col], v);   // streaming STG.128
    }
}

extern "C" void kernel_launch(void* const* d_in, const int* in_sizes, int n_in,
                              void* d_out, int out_size) {
    const int*   g;
    const float* pc;
    if (in_sizes[0] == Mv) {
        g  = (const int*)d_in[0];
        pc = (const float*)d_in[1];
    } else {
        g  = (const int*)d_in[1];
        pc = (const float*)d_in[0];
    }
    float* out = (float*)d_out;

    phase1_kernel<<<128, 256>>>(pc);

    // PDL launch of the write kernel: preamble overlaps with phase1 drain;
    // correctness guarded by cudaGridDependencySynchronize().
    cudaLaunchConfig_t cfg = {};
    cfg.gridDim  = dim3(Nv / 1024, Cv, ZSPLIT);
    cfg.blockDim = dim3(256, 1, 1);
    cfg.stream   = 0;
    cudaLaunchAttribute attr[1];
    attr[0].id = cudaLaunchAttributeProgrammaticStreamSerialization;
    attr[0].val.programmaticStreamSerializationAllowed = 1;
    cfg.attrs    = attr;
    cfg.numAttrs = 1;
    cudaLaunchKernelEx(&cfg, write_kernel, g, out);
}